// round 1
// baseline (speedup 1.0000x reference)
#include <cuda_runtime.h>
#include <cstdint>

#define BB   4096
#define TT   288
#define HIDN 64
#define GG   256           // 4*HIDN gate rows
#define NB   14            // batches per CTA
#define NTH  256
#define EPSF 1e-5f

__device__ float g_inv_den[TT];

typedef unsigned long long u64;

__device__ __forceinline__ u64 pack2(float a, float b) {
    u64 r; asm("mov.b64 %0, {%1, %2};" : "=l"(r) : "f"(a), "f"(b)); return r;
}
__device__ __forceinline__ u64 ffma2(u64 a, u64 b, u64 c) {
    u64 d; asm("fma.rn.f32x2 %0, %1, %2, %3;" : "=l"(d) : "l"(a), "l"(b), "l"(c)); return d;
}
__device__ __forceinline__ u64 fadd2(u64 a, u64 b) {
    u64 d; asm("add.rn.f32x2 %0, %1, %2;" : "=l"(d) : "l"(a), "l"(b)); return d;
}
__device__ __forceinline__ float2 unpk(u64 a) {
    float2 f; asm("mov.b64 {%0, %1}, %2;" : "=f"(f.x), "=f"(f.y) : "l"(a)); return f;
}
__device__ __forceinline__ float sigf(float x) {
    return __fdividef(1.f, 1.f + __expf(-x));
}
__device__ __forceinline__ float clipf(float v, float lo, float hi) {
    return fminf(fmaxf(v, lo), hi);
}

// ---------------------------------------------------------------------------
// Kernel A: per-timestep mask denominator (only cross-batch coupling), and
// zero the loss slot.
// ---------------------------------------------------------------------------
__global__ void den_kernel(const float* __restrict__ masks, float* __restrict__ out) {
    __shared__ float red[256];
    const int t = blockIdx.x;
    float s = 0.f;
    for (int b = threadIdx.x; b < BB; b += 256) {
        const float* p = masks + ((size_t)b * TT + t) * 2;
        s += p[0] + p[1];
    }
    red[threadIdx.x] = s;
    __syncthreads();
    for (int o = 128; o > 0; o >>= 1) {
        if (threadIdx.x < o) red[threadIdx.x] += red[threadIdx.x + o];
        __syncthreads();
    }
    if (threadIdx.x == 0) {
        g_inv_den[t] = __fdividef(1.f, red[0] + EPSF);
        if (t == 0) out[0] = 0.f;
    }
}

// ---------------------------------------------------------------------------
// Kernel B: persistent recurrent kernel. 293 CTAs x 256 threads, 14 batches
// per CTA, all 288 steps in-CTA. Thread = one gate row r (W_hh[r] packed as
// f32x2 in registers). Warp w additionally owns batches {w, w+8} for the
// scalar chain / pointwise LSTM (lane l -> hidden j in {l, l+32}).
// ---------------------------------------------------------------------------
__global__ void __launch_bounds__(NTH, 2) rnn_kernel(
    const float* __restrict__ Xg,  const float* __restrict__ XOg,
    const float* __restrict__ Mg,  const float* __restrict__ Dg,
    const float* __restrict__ MAXSR, const float* __restrict__ SRMEAN,
    const float* __restrict__ SRSTD,
    const float* __restrict__ Wgh, const float* __restrict__ Bgh,
    const float* __restrict__ Wgx, const float* __restrict__ Bgx,
    const float* __restrict__ Whist, const float* __restrict__ Bhist,
    const float* __restrict__ Wfr, const float* __restrict__ Bfr,
    const float* __restrict__ Wwc, const float* __restrict__ Bwc,
    const float* __restrict__ Wih, const float* __restrict__ Whh,
    const float* __restrict__ Bih, const float* __restrict__ Bhh,
    float* __restrict__ out)
{
    __shared__ __align__(16) float h_sm[NB][HIDN];
    __shared__ float  gates_sm[NB][GG];
    __shared__ __align__(16) float4 inp_sm[NB];
    __shared__ float  xb[2][NB][2], mb[2][NB][2], db[2][NB][2];
    __shared__ float  xob[2][NB][32];
    __shared__ float  invden_sm[TT];
    __shared__ float  loss_sm[8];

    const int bstart = blockIdx.x * NB;
    if (bstart >= BB) return;
    const int cnt = min(NB, BB - bstart);
    const int tid = threadIdx.x;
    const int w = tid >> 5, l = tid & 31;

    // ---- gate-row weights (registers) ----
    u64 whh2[32];
    {
        const float4* wr = reinterpret_cast<const float4*>(Whh + tid * HIDN);
#pragma unroll
        for (int k = 0; k < 16; k++) {
            float4 v = wr[k];
            whh2[2 * k]     = pack2(v.x, v.y);
            whh2[2 * k + 1] = pack2(v.z, v.w);
        }
    }
    const float4 wihv = *reinterpret_cast<const float4*>(Wih + tid * 4);
    const float biasg = Bih[tid] + Bhh[tid];

    // ---- lane-mapped small weights ----
    const int jA = l, jB = l + 32;
    const float wghA0 = Wgh[jA * 2], wghA1 = Wgh[jA * 2 + 1], bghA = Bgh[jA];
    const float wghB0 = Wgh[jB * 2], wghB1 = Wgh[jB * 2 + 1], bghB = Bgh[jB];
    const float whA0 = Whist[jA], whA1 = Whist[HIDN + jA];
    const float whB0 = Whist[jB], whB1 = Whist[HIDN + jB];
    const float wfr0l = (l == 0) ? 0.f : Wfr[l];          // feat_reg mask [0][0]=0
    const float wfr1l = (l == 1) ? 0.f : Wfr[33 + l];     // feat_reg mask [1][1]=0
    const float wfr0e = Wfr[32], wfr1e = Wfr[33 + 32];    // element 32 (xo[30])
    const float bh0 = Bhist[0], bh1 = Bhist[1], bfr0 = Bfr[0], bfr1 = Bfr[1];
    const float wgx0 = Wgx[0], wgx1 = Wgx[3], bgx0 = Bgx[0], bgx1 = Bgx[1];
    const float wc00 = Wwc[0], wc01 = Wwc[1], wc02 = Wwc[2], wc03 = Wwc[3];
    const float wc10 = Wwc[4], wc11 = Wwc[5], wc12 = Wwc[6], wc13 = Wwc[7];
    const float bwc0 = Bwc[0], bwc1 = Bwc[1];
    const float ub0 = (1.5f * MAXSR[0] - SRMEAN[0]) / SRSTD[0];
    const float ub1 = (1.5f * MAXSR[1] - SRMEAN[1]) / SRSTD[1];
    const float lb0 = (0.f - SRMEAN[0]) / SRSTD[0];
    const float lb1 = (0.f - SRMEAN[1]) / SRSTD[1];

    for (int i = tid; i < TT; i += NTH) invden_sm[i] = g_inv_den[i];
    for (int i = tid; i < NB * HIDN; i += NTH) (&h_sm[0][0])[i] = 0.f;

    float c1A = 0.f, c1B = 0.f, c2A = 0.f, c2B = 0.f;
    float lossAcc = 0.f;

    // ---- input prefetch machinery (double buffered) ----
    float pr[8];
    const int pb8 = tid >> 3, pq = tid & 7;
    const bool ldr = (tid < NB * 8) && (pb8 < cnt);
    auto issue = [&](int t) {
        if (ldr) {
            size_t bg = (size_t)(bstart + pb8);
            if (pq == 0) {
                float2 v = *reinterpret_cast<const float2*>(Xg + (bg * TT + t) * 2);
                pr[0] = v.x; pr[1] = v.y;
            } else if (pq == 1) {
                float2 v = *reinterpret_cast<const float2*>(Mg + (bg * TT + t) * 2);
                pr[0] = v.x; pr[1] = v.y;
            } else if (pq == 2) {
                float2 v = *reinterpret_cast<const float2*>(Dg + (bg * TT + t) * 2);
                pr[0] = v.x; pr[1] = v.y;
            } else {
                int k0 = (pq - 3) * 8;
                const float* p = XOg + (bg * TT + t) * 31 + k0;
                int n = min(8, 31 - k0);
#pragma unroll
                for (int i = 0; i < 8; i++) if (i < n) pr[i] = p[i];
            }
        }
    };
    auto commit = [&](int pb) {
        if (ldr) {
            if (pq == 0)      { xb[pb][pb8][0] = pr[0]; xb[pb][pb8][1] = pr[1]; }
            else if (pq == 1) { mb[pb][pb8][0] = pr[0]; mb[pb][pb8][1] = pr[1]; }
            else if (pq == 2) { db[pb][pb8][0] = pr[0]; db[pb][pb8][1] = pr[1]; }
            else {
                int k0 = (pq - 3) * 8;
                int n = min(8, 31 - k0);
#pragma unroll
                for (int i = 0; i < 8; i++) if (i < n) xob[pb][pb8][k0 + i] = pr[i];
            }
        }
    };

    // per-(warp,batch) scalar chain for one step
    auto do_batch = [&](int bb, int pb, int t) {
        const float x0 = xb[pb][bb][0], x1 = xb[pb][bb][1];
        const float m0 = mb[pb][bb][0], m1 = mb[pb][bb][1];
        const float d0 = db[pb][bb][0], d1 = db[pb][bb][1];
        // temporal decay of h + partial hist-reg dot
        float ga = __expf(-fmaxf(fmaf(d1, wghA1, fmaf(d0, wghA0, bghA)), 0.f));
        float gb = __expf(-fmaxf(fmaf(d1, wghB1, fmaf(d0, wghB0, bghB)), 0.f));
        float hA = h_sm[bb][jA] * ga;
        float hB = h_sm[bb][jB] * gb;
        h_sm[bb][jA] = hA;
        h_sm[bb][jB] = hB;
        float p0 = hA * whA0 + hB * whB0;
        float p1 = hA * whA1 + hB * whB1;
#pragma unroll
        for (int o = 16; o > 0; o >>= 1) {
            p0 += __shfl_xor_sync(0xffffffffu, p0, o);
            p1 += __shfl_xor_sync(0xffffffffu, p1, o);
        }
        float xh0 = clipf(p0 + bh0, lb0, ub0);
        float xh1 = clipf(p1 + bh1, lb1, ub1);
        float lnum = fabsf(x0 - xh0) * m0 + fabsf(x1 - xh1) * m1;
        float xc0 = m0 * x0 + (1.f - m0) * xh0;
        float xc1 = m1 * x1 + (1.f - m1) * xh1;
        // feat_reg over cat(x_c, x_obs): 33 elems distributed over lanes
        float vl = (l == 0) ? xc0 : (l == 1) ? xc1 : xob[pb][bb][l - 2];
        float q0 = wfr0l * vl;
        float q1 = wfr1l * vl;
        if (l == 0) {
            float xo30 = xob[pb][bb][30];
            q0 = fmaf(wfr0e, xo30, q0);
            q1 = fmaf(wfr1e, xo30, q1);
        }
#pragma unroll
        for (int o = 16; o > 0; o >>= 1) {
            q0 += __shfl_xor_sync(0xffffffffu, q0, o);
            q1 += __shfl_xor_sync(0xffffffffu, q1, o);
        }
        float zh0 = clipf(q0 + bfr0, lb0, ub0);
        float zh1 = clipf(q1 + bfr1, lb1, ub1);
        lnum += fabsf(x0 - zh0) * m0 + fabsf(x1 - zh1) * m1;
        float gx0 = __expf(-fmaxf(fmaf(d0, wgx0, bgx0), 0.f));
        float gx1 = __expf(-fmaxf(fmaf(d1, wgx1, bgx1), 0.f));
        float a0 = bwc0 + wc00 * gx0 + wc01 * gx1 + wc02 * m0 + wc03 * m1;
        float a1 = bwc1 + wc10 * gx0 + wc11 * gx1 + wc12 * m0 + wc13 * m1;
        float ch0 = clipf(a0 * zh0 + (1.f - a0) * xh0, lb0, ub0);
        float ch1 = clipf(a1 * zh1 + (1.f - a1) * xh1, lb1, ub1);
        lnum += fabsf(x0 - ch0) * m0 + fabsf(x1 - ch1) * m1;
        float cc0 = m0 * x0 + (1.f - m0) * ch0;
        float cc1 = m1 * x1 + (1.f - m1) * ch1;
        lossAcc += lnum * invden_sm[t];   // identical on all lanes; lane 0 used
        if (l == 0) {
            inp_sm[bb] = make_float4(cc0, cc1, m0, m1);
            size_t bg = (size_t)(bstart + bb);
            float* op = out + 1 + (bg * TT + (size_t)t) * 2;
            op[0] = cc0;
            op[1] = cc1;
        }
    };

    issue(0); commit(0);
    __syncthreads();

    for (int t = 0; t < TT; t++) {
        const int pb = t & 1;

        // ---- stage 1: decay + scalar chain for owned batches ----
        do_batch(w, pb, t);
        if (8 + w < cnt) do_batch(8 + w, pb, t);
        __syncthreads();

        // ---- stage 2: gate GEMV (f32x2 packed) + input prefetch ----
        if (t + 1 < TT) issue(t + 1);
        for (int bb = 0; bb < cnt; bb++) {
            const ulonglong2* h4 = reinterpret_cast<const ulonglong2*>(h_sm[bb]);
            u64 a0 = 0, a1 = 0, a2 = 0, a3 = 0;
#pragma unroll
            for (int k = 0; k < 8; k++) {
                ulonglong2 hv = h4[2 * k];
                ulonglong2 hw = h4[2 * k + 1];
                a0 = ffma2(whh2[4 * k + 0], hv.x, a0);
                a1 = ffma2(whh2[4 * k + 1], hv.y, a1);
                a2 = ffma2(whh2[4 * k + 2], hw.x, a2);
                a3 = ffma2(whh2[4 * k + 3], hw.y, a3);
            }
            float2 s = unpk(fadd2(fadd2(a0, a1), fadd2(a2, a3)));
            float4 inp = inp_sm[bb];
            float g = s.x + s.y + biasg
                    + wihv.x * inp.x + wihv.y * inp.y
                    + wihv.z * inp.z + wihv.w * inp.w;
            gates_sm[bb][tid] = g;
        }
        if (t + 1 < TT) commit(pb ^ 1);
        __syncthreads();

        // ---- stage 3: LSTM pointwise (c kept in registers) ----
        {
            int bb = w;
            float gi = gates_sm[bb][jA],       gf = gates_sm[bb][jA + 64];
            float gc = gates_sm[bb][jA + 128], go = gates_sm[bb][jA + 192];
            c1A = sigf(gf) * c1A + sigf(gi) * tanhf(gc);
            h_sm[bb][jA] = sigf(go) * tanhf(c1A);
            gi = gates_sm[bb][jB];       gf = gates_sm[bb][jB + 64];
            gc = gates_sm[bb][jB + 128]; go = gates_sm[bb][jB + 192];
            c1B = sigf(gf) * c1B + sigf(gi) * tanhf(gc);
            h_sm[bb][jB] = sigf(go) * tanhf(c1B);
            if (8 + w < cnt) {
                bb = 8 + w;
                gi = gates_sm[bb][jA];       gf = gates_sm[bb][jA + 64];
                gc = gates_sm[bb][jA + 128]; go = gates_sm[bb][jA + 192];
                c2A = sigf(gf) * c2A + sigf(gi) * tanhf(gc);
                h_sm[bb][jA] = sigf(go) * tanhf(c2A);
                gi = gates_sm[bb][jB];       gf = gates_sm[bb][jB + 64];
                gc = gates_sm[bb][jB + 128]; go = gates_sm[bb][jB + 192];
                c2B = sigf(gf) * c2B + sigf(gi) * tanhf(c2B * 0.f + gc);
                h_sm[bb][jB] = sigf(go) * tanhf(c2B);
            }
        }
        // no sync needed: stage3's h writes are re-read only by the same
        // thread (stage1) before the next __syncthreads.
    }

    if (l == 0) loss_sm[w] = lossAcc;
    __syncthreads();
    if (tid == 0) {
        float s = 0.f;
        for (int i = 0; i < 8; i++) s += loss_sm[i];
        atomicAdd(out, s);
    }
}

// ---------------------------------------------------------------------------
extern "C" void kernel_launch(void* const* d_in, const int* in_sizes, int n_in,
                              void* d_out, int out_size) {
    const float* X     = (const float*)d_in[0];
    const float* XO    = (const float*)d_in[1];
    const float* M     = (const float*)d_in[2];
    const float* D     = (const float*)d_in[3];
    const float* MAXSR = (const float*)d_in[4];
    const float* SRM   = (const float*)d_in[5];
    const float* SRS   = (const float*)d_in[6];
    const float* Wgh   = (const float*)d_in[7];
    const float* Bgh   = (const float*)d_in[8];
    const float* Wgx   = (const float*)d_in[9];
    const float* Bgx   = (const float*)d_in[10];
    const float* Whist = (const float*)d_in[11];
    const float* Bhist = (const float*)d_in[12];
    const float* Wfr   = (const float*)d_in[13];
    const float* Bfr   = (const float*)d_in[14];
    const float* Wwc   = (const float*)d_in[15];
    const float* Bwc   = (const float*)d_in[16];
    const float* Wih   = (const float*)d_in[17];
    const float* Whh   = (const float*)d_in[18];
    const float* Bih   = (const float*)d_in[19];
    const float* Bhh   = (const float*)d_in[20];
    float* out = (float*)d_out;

    den_kernel<<<TT, 256>>>(M, out);
    const int nblk = (BB + NB - 1) / NB;   // 293
    rnn_kernel<<<nblk, NTH>>>(X, XO, M, D, MAXSR, SRM, SRS,
                              Wgh, Bgh, Wgx, Bgx, Whist, Bhist,
                              Wfr, Bfr, Wwc, Bwc, Wih, Whh, Bih, Bhh, out);
}